// round 1
// baseline (speedup 1.0000x reference)
#include <cuda_runtime.h>
#include <cuda_bf16.h>

#define N 8192
#define D 128
#define NSPLIT 16          // column splits: 8192/16 = 512 cols per block
#define TILES_PER_SPLIT 4  // 512 / 128
#define TS 128             // tile size (rows and cols)
#define SA 129             // A smem row stride (pad: 8*129 mod 32 = 8 -> conflict-free)
#define TEMP_INV 10.0f

// Scratch (no cudaMalloc allowed)
__device__ float g_xn[N * D];          // normalized embeddings, 4 MB
__device__ float g_Zp[NSPLIT * N];     // partial sum of exp(logits), j != i
__device__ float g_Sp[NSPLIT * N];     // partial sum of positive logits
__device__ int   g_Pp[NSPLIT * N];     // partial positive counts

// ---------------------------------------------------------------------------
// Kernel 1: L2-normalize rows. One warp per row.
// ---------------------------------------------------------------------------
__global__ void norm_kernel(const float* __restrict__ x) {
    int row  = blockIdx.x * 8 + (threadIdx.x >> 5);
    int lane = threadIdx.x & 31;
    const float4 v = *(const float4*)(x + row * D + lane * 4);
    float ss = v.x * v.x + v.y * v.y + v.z * v.z + v.w * v.w;
    #pragma unroll
    for (int o = 16; o >= 1; o >>= 1)
        ss += __shfl_xor_sync(0xffffffffu, ss, o);
    float r = rsqrtf(ss);
    float4 o4 = make_float4(v.x * r, v.y * r, v.z * r, v.w * r);
    *(float4*)(g_xn + row * D + lane * 4) = o4;
}

// ---------------------------------------------------------------------------
// Kernel 2: fused pairwise logits + masked exp/logit reductions.
// Grid: (NSPLIT, N/TS). Block: 256 threads = 16x16, each thread 8x8 microtile.
// Per block: A-tile of 128 rows (resident), loop over 4 B-tiles of 128 cols.
// ---------------------------------------------------------------------------
__global__ void __launch_bounds__(256, 1)
pairwise_kernel(const long long* __restrict__ labels) {
    extern __shared__ float smem[];
    float* As = smem;                      // [128][SA]  row-major, padded
    float* Bs = As + TS * SA;              // [128][128] k-major (transposed)
    int* labA = (int*)(Bs + TS * TS);      // [128]
    int* labB = labA + TS;                 // [128]

    const int tid = threadIdx.x;
    const int tx  = tid & 15;              // 0..15 -> 8 columns each
    const int ty  = tid >> 4;              // 0..15 -> 8 rows each
    const int split = blockIdx.x;
    const int i0    = blockIdx.y * TS;

    // ---- Load A tile (coalesced, once per block) ----
    #pragma unroll
    for (int it = 0; it < 16; ++it) {
        int idx = it * 256 + tid;
        int i  = idx >> 5;
        int kc = (idx & 31) * 4;
        float4 v = *(const float4*)(g_xn + (i0 + i) * D + kc);
        float* dst = As + i * SA + kc;
        dst[0] = v.x; dst[1] = v.y; dst[2] = v.z; dst[3] = v.w;
    }
    if (tid < TS) labA[tid] = (int)labels[i0 + tid];
    __syncthreads();

    int labi[8];
    #pragma unroll
    for (int r = 0; r < 8; ++r) labi[r] = labA[ty * 8 + r];

    float zacc[8], sacc[8];
    int   pacc[8];
    #pragma unroll
    for (int r = 0; r < 8; ++r) { zacc[r] = 0.f; sacc[r] = 0.f; pacc[r] = 0; }

    for (int t = 0; t < TILES_PER_SPLIT; ++t) {
        const int j0 = split * (N / NSPLIT) + t * TS;
        __syncthreads();   // readers of previous Bs done

        // ---- Load B tile transposed: Bs[k][j]. Lanes span j -> STS conflict-free.
        #pragma unroll
        for (int it = 0; it < 16; ++it) {
            int idx  = it * 256 + tid;
            int lane = idx & 31;
            int grp  = idx >> 5;           // 0..127
            int jblk = grp >> 5;           // 0..3
            int kc   = (grp & 31) * 4;     // 0..124
            int j    = jblk * 32 + lane;
            float4 v = *(const float4*)(g_xn + (j0 + j) * D + kc);
            Bs[(kc + 0) * TS + j] = v.x;
            Bs[(kc + 1) * TS + j] = v.y;
            Bs[(kc + 2) * TS + j] = v.z;
            Bs[(kc + 3) * TS + j] = v.w;
        }
        if (tid < TS) labB[tid] = (int)labels[j0 + tid];
        __syncthreads();

        // ---- 128x128x128 fp32 tile GEMM, 8x8 per thread ----
        float acc[8][8];
        #pragma unroll
        for (int r = 0; r < 8; ++r)
            #pragma unroll
            for (int c = 0; c < 8; ++c) acc[r][c] = 0.f;

        const float* Ap = As + (ty * 8) * SA;
        const float* Bp = Bs + tx * 8;
        #pragma unroll 4
        for (int k = 0; k < D; ++k) {
            float a[8];
            #pragma unroll
            for (int r = 0; r < 8; ++r) a[r] = Ap[r * SA + k];
            float4 b0 = *(const float4*)(Bp + k * TS);
            float4 b1 = *(const float4*)(Bp + k * TS + 4);
            float b[8] = {b0.x, b0.y, b0.z, b0.w, b1.x, b1.y, b1.z, b1.w};
            #pragma unroll
            for (int r = 0; r < 8; ++r)
                #pragma unroll
                for (int c = 0; c < 8; ++c)
                    acc[r][c] += a[r] * b[c];
        }

        // ---- Fused epilogue: exp + masks ----
        int labj[8];
        #pragma unroll
        for (int c = 0; c < 8; ++c) labj[c] = labB[tx * 8 + c];

        #pragma unroll
        for (int r = 0; r < 8; ++r) {
            const int ig = i0 + ty * 8 + r;
            #pragma unroll
            for (int c = 0; c < 8; ++c) {
                const int jg = j0 + tx * 8 + c;
                float l = acc[r][c] * TEMP_INV;
                float e = __expf(l);
                if (jg != ig) {
                    zacc[r] += e;
                    if (labi[r] == labj[c]) { sacc[r] += l; pacc[r] += 1; }
                }
            }
        }
    }

    // ---- Reduce across the 16 tx lanes (within half-warp groups) ----
    #pragma unroll
    for (int r = 0; r < 8; ++r) {
        float z = zacc[r], s = sacc[r];
        int p = pacc[r];
        #pragma unroll
        for (int o = 8; o >= 1; o >>= 1) {
            z += __shfl_xor_sync(0xffffffffu, z, o);
            s += __shfl_xor_sync(0xffffffffu, s, o);
            p += __shfl_xor_sync(0xffffffffu, p, o);
        }
        if (tx == 0) {
            int i = i0 + ty * 8 + r;
            g_Zp[split * N + i] = z;
            g_Sp[split * N + i] = s;
            g_Pp[split * N + i] = p;
        }
    }
}

// ---------------------------------------------------------------------------
// Kernel 3: combine partials -> scalar loss
// ---------------------------------------------------------------------------
__global__ void finalize_kernel(float* __restrict__ out) {
    __shared__ float s_l[256];
    __shared__ float s_c[256];
    const int tid = threadIdx.x;
    float lsum = 0.f, vcnt = 0.f;
    for (int i = tid; i < N; i += 256) {
        float Z = 0.f, S = 0.f;
        int P = 0;
        #pragma unroll
        for (int sp = 0; sp < NSPLIT; ++sp) {
            Z += g_Zp[sp * N + i];
            S += g_Sp[sp * N + i];
            P += g_Pp[sp * N + i];
        }
        if (P > 0) {
            lsum += S / (float)P - logf(Z);
            vcnt += 1.f;
        }
    }
    s_l[tid] = lsum; s_c[tid] = vcnt;
    __syncthreads();
    for (int o = 128; o >= 1; o >>= 1) {
        if (tid < o) { s_l[tid] += s_l[tid + o]; s_c[tid] += s_c[tid + o]; }
        __syncthreads();
    }
    if (tid == 0) out[0] = -s_l[0] / s_c[0];
}

// ---------------------------------------------------------------------------
extern "C" void kernel_launch(void* const* d_in, const int* in_sizes, int n_in,
                              void* d_out, int out_size) {
    const float* feats      = (const float*)d_in[0];
    const long long* labels = (const long long*)d_in[1];
    float* out = (float*)d_out;

    static int smem_set = 0;
    const int smem_bytes = (TS * SA + TS * TS) * (int)sizeof(float) + 2 * TS * (int)sizeof(int);
    // attribute set is idempotent and not a stream op; safe under capture
    cudaFuncSetAttribute(pairwise_kernel, cudaFuncAttributeMaxDynamicSharedMemorySize, smem_bytes);
    (void)smem_set;

    norm_kernel<<<N / 8, 256>>>(feats);
    pairwise_kernel<<<dim3(NSPLIT, N / TS), 256, smem_bytes>>>(labels);
    finalize_kernel<<<1, 256>>>(out);
}

// round 3
// speedup vs baseline: 2.2881x; 2.2881x over previous
#include <cuda_runtime.h>
#include <cuda_fp16.h>
#include <cstdint>

#define N 8192
#define D 128
#define TSZ 128
#define NSPLIT 256          // 64 col-tiles * 4 warp-columns
#define TEMP_INV 10.0f

// ---------------- scratch (no cudaMalloc allowed) ----------------
__device__ unsigned short g_hi[N * D];       // fp16 hi part, 2 MB
__device__ unsigned short g_lo[N * D];       // fp16 lo part, 2 MB
__device__ float g_Zp[(size_t)N * NSPLIT];   // 8 MB, [row][split]
__device__ float g_Sp[(size_t)N * NSPLIT];   // 8 MB
__device__ int   g_Pp[(size_t)N * NSPLIT];   // 8 MB
__device__ float g_row[N];
__device__ float g_vld[N];

// ---------------- smem geometry ----------------
#define STRIDE_B 272                 // bytes per 128-half row (16B pad: conflict-free ldmatrix)
#define TILE_B   (128 * STRIDE_B)    // 34816
#define OF_AHI   0
#define OF_ALO   (TILE_B)
#define OF_BHI   (2 * TILE_B)
#define OF_BLO   (3 * TILE_B)
#define OF_LABA  (4 * TILE_B)        // 139264
#define OF_LABB  (OF_LABA + 512)
#define SMEM_REQ (OF_LABB + 512)     // 140288

__device__ __forceinline__ uint32_t smem_to_u32(const void* p) {
    uint32_t a;
    asm("{ .reg .u64 t; cvta.to.shared.u64 t, %1; cvt.u32.u64 %0, t; }" : "=r"(a) : "l"(p));
    return a;
}
__device__ __forceinline__ void ldsm4(uint32_t* r, uint32_t addr) {
    asm volatile("ldmatrix.sync.aligned.m8n8.x4.shared.b16 {%0,%1,%2,%3}, [%4];"
        : "=r"(r[0]), "=r"(r[1]), "=r"(r[2]), "=r"(r[3]) : "r"(addr));
}
__device__ __forceinline__ void mma16816(float* c, const uint32_t* a, const uint32_t* b) {
    asm volatile("mma.sync.aligned.m16n8k16.row.col.f32.f16.f16.f32 "
        "{%0,%1,%2,%3}, {%4,%5,%6,%7}, {%8,%9}, {%0,%1,%2,%3};"
        : "+f"(c[0]), "+f"(c[1]), "+f"(c[2]), "+f"(c[3])
        : "r"(a[0]), "r"(a[1]), "r"(a[2]), "r"(a[3]), "r"(b[0]), "r"(b[1]));
}

// ---------------------------------------------------------------------------
// Kernel 1: L2-normalize + fp16 hi/lo split. One warp per row.
// ---------------------------------------------------------------------------
__global__ void norm_kernel(const float* __restrict__ x) {
    int row  = blockIdx.x * 8 + (threadIdx.x >> 5);
    int lane = threadIdx.x & 31;
    const float4 v = *(const float4*)(x + row * D + lane * 4);
    float ss = v.x * v.x + v.y * v.y + v.z * v.z + v.w * v.w;
    #pragma unroll
    for (int o = 16; o >= 1; o >>= 1) ss += __shfl_xor_sync(0xffffffffu, ss, o);
    float r = rsqrtf(ss);
    float xs[4] = {v.x * r, v.y * r, v.z * r, v.w * r};
    unsigned short hs[4], ls[4];
    #pragma unroll
    for (int i = 0; i < 4; ++i) {
        __half h  = __float2half_rn(xs[i]);
        __half lo = __float2half_rn(xs[i] - __half2float(h));
        hs[i] = __half_as_ushort(h);
        ls[i] = __half_as_ushort(lo);
    }
    *(ushort4*)(g_hi + row * D + lane * 4) = make_ushort4(hs[0], hs[1], hs[2], hs[3]);
    *(ushort4*)(g_lo + row * D + lane * 4) = make_ushort4(ls[0], ls[1], ls[2], ls[3]);
}

// ---------------------------------------------------------------------------
// Kernel 2: 128x128 logits tile per block, HMMA (mma.sync) 3-pass fp16 split,
// epilogue fused on register accumulators.
// Grid (64, 64): bx = col tile, by = row tile. 256 threads = 8 warps (2m x 4n).
// ---------------------------------------------------------------------------
__global__ void __launch_bounds__(256, 1)
pairwise_kernel(const long long* __restrict__ labels) {
    extern __shared__ char smem[];
    const uint32_t smb = smem_to_u32(smem);

    const int tid  = threadIdx.x;
    const int wid  = tid >> 5;
    const int lane = tid & 31;
    const int wm   = wid >> 2;       // 0..1  -> 64-row slab
    const int wn   = wid & 3;        // 0..3  -> 32-col slab
    const int bx = blockIdx.x, by = blockIdx.y;
    const int i0 = by * TSZ, j0 = bx * TSZ;

    // ---- fill 4 tiles: Ahi/Alo (rows i0..), Bhi/Blo (rows j0..) ----
    // 4 tiles * 128 rows * 16 chunks(16B) = 8192 chunks; 32 iters of 256 threads.
    {
        const char* ghi = (const char*)g_hi;
        const char* glo = (const char*)g_lo;
        #pragma unroll
        for (int it = 0; it < 32; ++it) {
            int idx   = it * 256 + tid;
            int tile  = idx >> 11;         // 0..3
            int rem   = idx & 2047;
            int row   = rem >> 4;
            int chunk = rem & 15;
            const char* src = (tile == 0) ? ghi : (tile == 1) ? glo : (tile == 2) ? ghi : glo;
            int grow = ((tile < 2) ? i0 : j0) + row;
            uint4 v = *(const uint4*)(src + (size_t)grow * 256 + chunk * 16);
            *(uint4*)(smem + tile * TILE_B + row * STRIDE_B + chunk * 16) = v;
        }
        if (tid < 128) {
            ((int*)(smem + OF_LABA))[tid] = (int)labels[i0 + tid];
            ((int*)(smem + OF_LABB))[tid] = (int)labels[j0 + tid];
        }
    }
    __syncthreads();

    // ---- fragment base addresses ----
    // A: lane l -> row (l&15), k-halfword offset (l>>4)*8 elems (=16B)
    const uint32_t aBase = smb + (uint32_t)((wm * 64 + (lane & 15)) * STRIDE_B + (lane >> 4) * 16);
    // B: lane l -> n row (l&7) + ((l>>4)<<3), k-half ((l>>3)&1)*8 elems
    const uint32_t bBase = smb + (uint32_t)((wn * 32 + (lane & 7) + ((lane >> 4) << 3)) * STRIDE_B
                                            + ((lane >> 3) & 1) * 16);

    float acc[4][4][4];
    #pragma unroll
    for (int mi = 0; mi < 4; ++mi)
        #pragma unroll
        for (int ni = 0; ni < 4; ++ni)
            #pragma unroll
            for (int r = 0; r < 4; ++r) acc[mi][ni][r] = 0.f;

    #pragma unroll
    for (int ks = 0; ks < 8; ++ks) {
        const uint32_t ko = (uint32_t)(ks * 32);   // 16 halves = 32 bytes
        uint32_t ahi[4][4], alo[4][4], bhi[4][2], blo[4][2];
        #pragma unroll
        for (int mi = 0; mi < 4; ++mi) {
            ldsm4(ahi[mi], aBase + OF_AHI + mi * (16 * STRIDE_B) + ko);
            ldsm4(alo[mi], aBase + OF_ALO + mi * (16 * STRIDE_B) + ko);
        }
        uint32_t t0[4], t1[4];
        ldsm4(t0, bBase + OF_BHI + ko);
        ldsm4(t1, bBase + OF_BHI + 16 * STRIDE_B + ko);
        bhi[0][0] = t0[0]; bhi[0][1] = t0[1]; bhi[1][0] = t0[2]; bhi[1][1] = t0[3];
        bhi[2][0] = t1[0]; bhi[2][1] = t1[1]; bhi[3][0] = t1[2]; bhi[3][1] = t1[3];
        ldsm4(t0, bBase + OF_BLO + ko);
        ldsm4(t1, bBase + OF_BLO + 16 * STRIDE_B + ko);
        blo[0][0] = t0[0]; blo[0][1] = t0[1]; blo[1][0] = t0[2]; blo[1][1] = t0[3];
        blo[2][0] = t1[0]; blo[2][1] = t1[1]; blo[3][0] = t1[2]; blo[3][1] = t1[3];

        #pragma unroll
        for (int mi = 0; mi < 4; ++mi)
            #pragma unroll
            for (int ni = 0; ni < 4; ++ni) {
                mma16816(acc[mi][ni], ahi[mi], bhi[ni]);   // hi*hi
                mma16816(acc[mi][ni], ahi[mi], blo[ni]);   // hi*lo
                mma16816(acc[mi][ni], alo[mi], bhi[ni]);   // lo*hi
            }
    }

    // ---- fused epilogue on register accumulators ----
    const int tq = lane >> 2;       // 0..7 : row within 8-row group
    const int tr = lane & 3;        // 0..3 : col pair within 8-col tile
    const int* labAs = (const int*)(smem + OF_LABA);
    const int* labBs = (const int*)(smem + OF_LABB);

    int labi[4][2];
    #pragma unroll
    for (int mi = 0; mi < 4; ++mi)
        #pragma unroll
        for (int h = 0; h < 2; ++h)
            labi[mi][h] = labAs[wm * 64 + mi * 16 + h * 8 + tq];

    float z[4][2], s[4][2];
    int p[4][2];
    #pragma unroll
    for (int mi = 0; mi < 4; ++mi)
        #pragma unroll
        for (int h = 0; h < 2; ++h) { z[mi][h] = 0.f; s[mi][h] = 0.f; p[mi][h] = 0; }

    #pragma unroll
    for (int ni = 0; ni < 4; ++ni) {
        const int jc  = j0 + wn * 32 + ni * 8 + tr * 2;
        const int lj0 = labBs[wn * 32 + ni * 8 + tr * 2];
        const int lj1 = labBs[wn * 32 + ni * 8 + tr * 2 + 1];
        #pragma unroll
        for (int mi = 0; mi < 4; ++mi)
            #pragma unroll
            for (int h = 0; h < 2; ++h) {
                const int ig = i0 + wm * 64 + mi * 16 + h * 8 + tq;
                float l0 = acc[mi][ni][h * 2 + 0] * TEMP_INV;
                float l1 = acc[mi][ni][h * 2 + 1] * TEMP_INV;
                float e0 = __expf(l0), e1 = __expf(l1);
                if (jc != ig) {
                    z[mi][h] += e0;
                    if (labi[mi][h] == lj0) { s[mi][h] += l0; p[mi][h] += 1; }
                }
                if (jc + 1 != ig) {
                    z[mi][h] += e1;
                    if (labi[mi][h] == lj1) { s[mi][h] += l1; p[mi][h] += 1; }
                }
            }
    }

    // reduce over the 4 'tr' lanes, then write partials (split = bx*4 + wn)
    const int sp = bx * 4 + wn;
    #pragma unroll
    for (int mi = 0; mi < 4; ++mi)
        #pragma unroll
        for (int h = 0; h < 2; ++h) {
            float zz = z[mi][h], ss = s[mi][h];
            int pp = p[mi][h];
            zz += __shfl_xor_sync(0xffffffffu, zz, 1);
            ss += __shfl_xor_sync(0xffffffffu, ss, 1);
            pp += __shfl_xor_sync(0xffffffffu, pp, 1);
            zz += __shfl_xor_sync(0xffffffffu, zz, 2);
            ss += __shfl_xor_sync(0xffffffffu, ss, 2);
            pp += __shfl_xor_sync(0xffffffffu, pp, 2);
            if (tr == 0) {
                int row = i0 + wm * 64 + mi * 16 + h * 8 + tq;
                g_Zp[(size_t)row * NSPLIT + sp] = zz;
                g_Sp[(size_t)row * NSPLIT + sp] = ss;
                g_Pp[(size_t)row * NSPLIT + sp] = pp;
            }
        }
}

// ---------------------------------------------------------------------------
// Kernel 3: per-row combine (warp per row, coalesced over [row][256] partials)
// ---------------------------------------------------------------------------
__global__ void rowreduce_kernel() {
    int gw   = (blockIdx.x * 256 + threadIdx.x) >> 5;   // global warp = row
    int lane = threadIdx.x & 31;
    float z = 0.f, s = 0.f;
    int p = 0;
    #pragma unroll
    for (int k = 0; k < NSPLIT / 32; ++k) {
        int sp = lane + 32 * k;
        z += g_Zp[(size_t)gw * NSPLIT + sp];
        s += g_Sp[(size_t)gw * NSPLIT + sp];
        p += g_Pp[(size_t)gw * NSPLIT + sp];
    }
    #pragma unroll
    for (int o = 16; o >= 1; o >>= 1) {
        z += __shfl_xor_sync(0xffffffffu, z, o);
        s += __shfl_xor_sync(0xffffffffu, s, o);
        p += __shfl_xor_sync(0xffffffffu, p, o);
    }
    if (lane == 0) {
        if (p > 0) { g_row[gw] = s / (float)p - logf(z); g_vld[gw] = 1.f; }
        else       { g_row[gw] = 0.f;                    g_vld[gw] = 0.f; }
    }
}

// ---------------------------------------------------------------------------
// Kernel 4: final scalar
// ---------------------------------------------------------------------------
__global__ void final_kernel(float* __restrict__ out) {
    __shared__ float s_l[256], s_c[256];
    const int tid = threadIdx.x;
    float lsum = 0.f, vcnt = 0.f;
    for (int i = tid; i < N; i += 256) { lsum += g_row[i]; vcnt += g_vld[i]; }
    s_l[tid] = lsum; s_c[tid] = vcnt;
    __syncthreads();
    for (int o = 128; o >= 1; o >>= 1) {
        if (tid < o) { s_l[tid] += s_l[tid + o]; s_c[tid] += s_c[tid + o]; }
        __syncthreads();
    }
    if (tid == 0) out[0] = -s_l[0] / s_c[0];
}

// ---------------------------------------------------------------------------
extern "C" void kernel_launch(void* const* d_in, const int* in_sizes, int n_in,
                              void* d_out, int out_size) {
    const float* feats      = (const float*)d_in[0];
    const long long* labels = (const long long*)d_in[1];
    float* out = (float*)d_out;

    cudaFuncSetAttribute(pairwise_kernel, cudaFuncAttributeMaxDynamicSharedMemorySize, SMEM_REQ);

    norm_kernel<<<N / 8, 256>>>(feats);
    pairwise_kernel<<<dim3(64, 64), 256, SMEM_REQ>>>(labels);
    rowreduce_kernel<<<N * 32 / 256, 256>>>();
    final_kernel<<<1, 256>>>(out);
}

// round 5
// speedup vs baseline: 3.6311x; 1.5869x over previous
#include <cuda_runtime.h>
#include <cuda_fp16.h>
#include <cstdint>

#define N 8192
#define D 128
#define TSZ 128
#define NTILE 64
#define NBLK (NTILE * (NTILE + 1) / 2)   // 2080 triangular blocks
#define NSPLIT 512                       // 64 tiles * 8 (wn*2 + role/wm)
#define TEMP_INV 10.0f

// ---------------- scratch (no cudaMalloc allowed) ----------------
__device__ unsigned short g_hi[N * D];       // fp16 hi part, 2 MB
__device__ unsigned short g_lo[N * D];       // fp16 lo part, 2 MB
__device__ float g_Zp[(size_t)N * NSPLIT];   // 16 MB, zero-init, unwritten slots stay 0
__device__ float g_Sp[(size_t)N * NSPLIT];   // 16 MB
__device__ int   g_Pp[(size_t)N * NSPLIT];   // 16 MB
__device__ float g_blkL[N / 8];
__device__ float g_blkC[N / 8];

// ---------------- smem geometry ----------------
#define STRIDE_B 272                 // bytes per 128-half row (16B pad)
#define TILE_B   (128 * STRIDE_B)    // 34816
#define OF_AHI   0
#define OF_BHI   (2 * TILE_B)        // (ALO = AHI+TILE_B, BLO = BHI+TILE_B)
#define OF_LABA  (4 * TILE_B)
#define OF_LABB  (OF_LABA + 512)
#define SMEM_REQ (OF_LABB + 512)

__device__ __forceinline__ uint32_t smem_to_u32(const void* p) {
    uint32_t a;
    asm("{ .reg .u64 t; cvta.to.shared.u64 t, %1; cvt.u32.u64 %0, t; }" : "=r"(a) : "l"(p));
    return a;
}
__device__ __forceinline__ void ldsm4(uint32_t* r, uint32_t addr) {
    asm volatile("ldmatrix.sync.aligned.m8n8.x4.shared.b16 {%0,%1,%2,%3}, [%4];"
        : "=r"(r[0]), "=r"(r[1]), "=r"(r[2]), "=r"(r[3]) : "r"(addr));
}
__device__ __forceinline__ void mma16816(float* c, const uint32_t* a, const uint32_t* b) {
    asm volatile("mma.sync.aligned.m16n8k16.row.col.f32.f16.f16.f32 "
        "{%0,%1,%2,%3}, {%4,%5,%6,%7}, {%8,%9}, {%0,%1,%2,%3};"
        : "+f"(c[0]), "+f"(c[1]), "+f"(c[2]), "+f"(c[3])
        : "r"(a[0]), "r"(a[1]), "r"(a[2]), "r"(a[3]), "r"(b[0]), "r"(b[1]));
}

// ---------------------------------------------------------------------------
// Kernel 1: L2-normalize + fp16 hi/lo split. One warp per row.
// ---------------------------------------------------------------------------
__global__ void norm_kernel(const float* __restrict__ x) {
    int row  = blockIdx.x * 8 + (threadIdx.x >> 5);
    int lane = threadIdx.x & 31;
    const float4 v = *(const float4*)(x + row * D + lane * 4);
    float ss = v.x * v.x + v.y * v.y + v.z * v.z + v.w * v.w;
    #pragma unroll
    for (int o = 16; o >= 1; o >>= 1) ss += __shfl_xor_sync(0xffffffffu, ss, o);
    float r = rsqrtf(ss);
    float xs[4] = {v.x * r, v.y * r, v.z * r, v.w * r};
    unsigned short hs[4], ls[4];
    #pragma unroll
    for (int i = 0; i < 4; ++i) {
        __half h  = __float2half_rn(xs[i]);
        __half lo = __float2half_rn(xs[i] - __half2float(h));
        hs[i] = __half_as_ushort(h);
        ls[i] = __half_as_ushort(lo);
    }
    *(ushort4*)(g_hi + row * D + lane * 4) = make_ushort4(hs[0], hs[1], hs[2], hs[3]);
    *(ushort4*)(g_lo + row * D + lane * 4) = make_ushort4(ls[0], ls[1], ls[2], ls[3]);
}

// ---------------------------------------------------------------------------
// Kernel 2: triangular 128x128 tiles (by <= bx), HMMA 3-pass fp16 split.
// Epilogue extracts row sums (rows i0..) and, for off-diagonal tiles,
// column sums (= mirror tile's row sums, rows j0..).
// Grid: NBLK 1D; 256 threads = 8 warps (2m x 4n).
// ---------------------------------------------------------------------------
__global__ void __launch_bounds__(256, 1)
pairwise_kernel(const long long* __restrict__ labels) {
    // triangular decode: t -> (bx, by) with 0 <= by <= bx < 64
    const int t = blockIdx.x;
    int bx = (int)((sqrtf(8.0f * (float)t + 1.0f) - 1.0f) * 0.5f);
    while ((bx + 1) * (bx + 2) / 2 <= t) ++bx;
    while (bx * (bx + 1) / 2 > t) --bx;
    const int by = t - bx * (bx + 1) / 2;
    const bool diag = (by == bx);

    extern __shared__ char smem[];
    const uint32_t smb = smem_to_u32(smem);

    const int tid  = threadIdx.x;
    const int wid  = tid >> 5;
    const int lane = tid & 31;
    const int wm   = wid >> 2;       // 0..1  -> 64-row slab
    const int wn   = wid & 3;        // 0..3  -> 32-col slab
    const int i0 = by * TSZ, j0 = bx * TSZ;

    // ---- fill smem tiles ----
    {
        const char* ghi = (const char*)g_hi;
        const char* glo = (const char*)g_lo;
        #pragma unroll
        for (int it = 0; it < 16; ++it) {
            int idx   = it * 256 + tid;
            int tile  = idx >> 11;         // 0=hi 1=lo
            int rem   = idx & 2047;
            int row   = rem >> 4;
            int chunk = rem & 15;
            const char* src = tile ? glo : ghi;
            uint4 v = *(const uint4*)(src + (size_t)(i0 + row) * 256 + chunk * 16);
            *(uint4*)(smem + OF_AHI + tile * TILE_B + row * STRIDE_B + chunk * 16) = v;
        }
        if (!diag) {
            #pragma unroll
            for (int it = 0; it < 16; ++it) {
                int idx   = it * 256 + tid;
                int tile  = idx >> 11;
                int rem   = idx & 2047;
                int row   = rem >> 4;
                int chunk = rem & 15;
                const char* src = tile ? glo : ghi;
                uint4 v = *(const uint4*)(src + (size_t)(j0 + row) * 256 + chunk * 16);
                *(uint4*)(smem + OF_BHI + tile * TILE_B + row * STRIDE_B + chunk * 16) = v;
            }
        }
        if (tid < 128) {
            ((int*)(smem + OF_LABA))[tid] = (int)labels[i0 + tid];
            ((int*)(smem + OF_LABB))[tid] = (int)labels[j0 + tid];
        }
    }
    __syncthreads();

    const uint32_t bTile = diag ? (uint32_t)OF_AHI : (uint32_t)OF_BHI;
    const uint32_t aBase = smb + (uint32_t)((wm * 64 + (lane & 15)) * STRIDE_B + (lane >> 4) * 16);
    const uint32_t bBase = smb + bTile
                         + (uint32_t)((wn * 32 + (lane & 7) + ((lane >> 4) << 3)) * STRIDE_B
                                      + ((lane >> 3) & 1) * 16);

    float acc[4][4][4];
    #pragma unroll
    for (int mi = 0; mi < 4; ++mi)
        #pragma unroll
        for (int ni = 0; ni < 4; ++ni)
            #pragma unroll
            for (int r = 0; r < 4; ++r) acc[mi][ni][r] = 0.f;

    #pragma unroll
    for (int ks = 0; ks < 8; ++ks) {
        const uint32_t ko = (uint32_t)(ks * 32);
        uint32_t ahi[4][4], alo[4][4], bhi[4][2], blo[4][2];
        #pragma unroll
        for (int mi = 0; mi < 4; ++mi) {
            ldsm4(ahi[mi], aBase + OF_AHI + mi * (16 * STRIDE_B) + ko);
            ldsm4(alo[mi], aBase + OF_AHI + TILE_B + mi * (16 * STRIDE_B) + ko);
        }
        uint32_t t0[4], t1[4];
        ldsm4(t0, bBase + ko);
        ldsm4(t1, bBase + 16 * STRIDE_B + ko);
        bhi[0][0] = t0[0]; bhi[0][1] = t0[1]; bhi[1][0] = t0[2]; bhi[1][1] = t0[3];
        bhi[2][0] = t1[0]; bhi[2][1] = t1[1]; bhi[3][0] = t1[2]; bhi[3][1] = t1[3];
        ldsm4(t0, bBase + TILE_B + ko);
        ldsm4(t1, bBase + TILE_B + 16 * STRIDE_B + ko);
        blo[0][0] = t0[0]; blo[0][1] = t0[1]; blo[1][0] = t0[2]; blo[1][1] = t0[3];
        blo[2][0] = t1[0]; blo[2][1] = t1[1]; blo[3][0] = t1[2]; blo[3][1] = t1[3];

        #pragma unroll
        for (int mi = 0; mi < 4; ++mi)
            #pragma unroll
            for (int ni = 0; ni < 4; ++ni) {
                mma16816(acc[mi][ni], ahi[mi], bhi[ni]);
                mma16816(acc[mi][ni], ahi[mi], blo[ni]);
                mma16816(acc[mi][ni], alo[mi], bhi[ni]);
            }
    }

    // ---- fused epilogue ----
    const int tq = lane >> 2;       // 0..7
    const int tr = lane & 3;        // 0..3
    const int* labAs = (const int*)(smem + OF_LABA);
    const int* labBs = (const int*)(smem + OF_LABB);

    int labi[4][2];
    #pragma unroll
    for (int mi = 0; mi < 4; ++mi)
        #pragma unroll
        for (int h = 0; h < 2; ++h)
            labi[mi][h] = labAs[wm * 64 + mi * 16 + h * 8 + tq];

    float rz[4][2], rs[4][2], cz[4][2], cs[4][2];
    int   rp[4][2], cp[4][2];
    #pragma unroll
    for (int a = 0; a < 4; ++a)
        #pragma unroll
        for (int b = 0; b < 2; ++b) {
            rz[a][b] = rs[a][b] = cz[a][b] = cs[a][b] = 0.f;
            rp[a][b] = cp[a][b] = 0;
        }

    #pragma unroll
    for (int ni = 0; ni < 4; ++ni) {
        const int jc  = j0 + wn * 32 + ni * 8 + tr * 2;
        const int lj0 = labBs[wn * 32 + ni * 8 + tr * 2];
        const int lj1 = labBs[wn * 32 + ni * 8 + tr * 2 + 1];
        #pragma unroll
        for (int mi = 0; mi < 4; ++mi)
            #pragma unroll
            for (int h = 0; h < 2; ++h) {
                const int ig = i0 + wm * 64 + mi * 16 + h * 8 + tq;
                float l0 = acc[mi][ni][h * 2 + 0] * TEMP_INV;
                float l1 = acc[mi][ni][h * 2 + 1] * TEMP_INV;
                float e0 = __expf(l0), e1 = __expf(l1);
                bool m0 = (labi[mi][h] == lj0);
                bool m1 = (labi[mi][h] == lj1);
                if (!(diag && jc == ig))     { rz[mi][h] += e0; if (m0) { rs[mi][h] += l0; rp[mi][h] += 1; } }
                if (!(diag && jc + 1 == ig)) { rz[mi][h] += e1; if (m1) { rs[mi][h] += l1; rp[mi][h] += 1; } }
                cz[ni][0] += e0; if (m0) { cs[ni][0] += l0; cp[ni][0] += 1; }
                cz[ni][1] += e1; if (m1) { cs[ni][1] += l1; cp[ni][1] += 1; }
            }
    }

    // row partials: reduce over tr lanes (xor 1,2), split = bx*8 + wn*2
    {
        const int sp = bx * 8 + wn * 2;
        #pragma unroll
        for (int mi = 0; mi < 4; ++mi)
            #pragma unroll
            for (int h = 0; h < 2; ++h) {
                float zz = rz[mi][h], ss = rs[mi][h];
                int pp = rp[mi][h];
                #pragma unroll
                for (int o = 1; o <= 2; o <<= 1) {
                    zz += __shfl_xor_sync(0xffffffffu, zz, o);
                    ss += __shfl_xor_sync(0xffffffffu, ss, o);
                    pp += __shfl_xor_sync(0xffffffffu, pp, o);
                }
                if (tr == 0) {
                    int row = i0 + wm * 64 + mi * 16 + h * 8 + tq;
                    g_Zp[(size_t)row * NSPLIT + sp] = zz;
                    g_Sp[(size_t)row * NSPLIT + sp] = ss;
                    g_Pp[(size_t)row * NSPLIT + sp] = pp;
                }
            }
    }

    // column partials (mirror rows): reduce over tq lanes (xor 4,8,16),
    // split = by*8 + wn*2 + wm  (< bx*8 since by < bx for non-diag)
    if (!diag) {
        const int sp = by * 8 + wn * 2 + wm;
        #pragma unroll
        for (int ni = 0; ni < 4; ++ni)
            #pragma unroll
            for (int c = 0; c < 2; ++c) {
                float zz = cz[ni][c], ss = cs[ni][c];
                int pp = cp[ni][c];
                #pragma unroll
                for (int o = 4; o <= 16; o <<= 1) {
                    zz += __shfl_xor_sync(0xffffffffu, zz, o);
                    ss += __shfl_xor_sync(0xffffffffu, ss, o);
                    pp += __shfl_xor_sync(0xffffffffu, pp, o);
                }
                if (tq == 0) {
                    int row = j0 + wn * 32 + ni * 8 + tr * 2 + c;
                    g_Zp[(size_t)row * NSPLIT + sp] = zz;
                    g_Sp[(size_t)row * NSPLIT + sp] = ss;
                    g_Pp[(size_t)row * NSPLIT + sp] = pp;
                }
            }
    }
}

// ---------------------------------------------------------------------------
// Kernel 3: per-row combine (warp per row) + per-block loss partial
// ---------------------------------------------------------------------------
__global__ void rowreduce_kernel() {
    __shared__ float bl[8], bc[8];
    const int warp = threadIdx.x >> 5;
    const int row  = blockIdx.x * 8 + warp;
    const int lane = threadIdx.x & 31;
    float z = 0.f, s = 0.f;
    int p = 0;
    #pragma unroll
    for (int k = 0; k < NSPLIT / 32; ++k) {
        int sp = lane + 32 * k;
        z += g_Zp[(size_t)row * NSPLIT + sp];
        s += g_Sp[(size_t)row * NSPLIT + sp];
        p += g_Pp[(size_t)row * NSPLIT + sp];
    }
    #pragma unroll
    for (int o = 16; o >= 1; o >>= 1) {
        z += __shfl_xor_sync(0xffffffffu, z, o);
        s += __shfl_xor_sync(0xffffffffu, s, o);
        p += __shfl_xor_sync(0xffffffffu, p, o);
    }
    if (lane == 0) {
        if (p > 0) { bl[warp] = s / (float)p - logf(z); bc[warp] = 1.f; }
        else       { bl[warp] = 0.f;                    bc[warp] = 0.f; }
    }
    __syncthreads();
    if (threadIdx.x == 0) {
        float L = 0.f, C = 0.f;
        #pragma unroll
        for (int w = 0; w < 8; ++w) { L += bl[w]; C += bc[w]; }
        g_blkL[blockIdx.x] = L;
        g_blkC[blockIdx.x] = C;
    }
}

// ---------------------------------------------------------------------------
// Kernel 4: final scalar over N/8 = 1024 block partials
// ---------------------------------------------------------------------------
__global__ void final_kernel(float* __restrict__ out) {
    __shared__ float s_l[256], s_c[256];
    const int tid = threadIdx.x;
    float lsum = 0.f, vcnt = 0.f;
    #pragma unroll
    for (int k = 0; k < 4; ++k) {
        lsum += g_blkL[tid + 256 * k];
        vcnt += g_blkC[tid + 256 * k];
    }
    s_l[tid] = lsum; s_c[tid] = vcnt;
    __syncthreads();
    for (int o = 128; o >= 1; o >>= 1) {
        if (tid < o) { s_l[tid] += s_l[tid + o]; s_c[tid] += s_c[tid + o]; }
        __syncthreads();
    }
    if (tid == 0) out[0] = -s_l[0] / s_c[0];
}

// ---------------------------------------------------------------------------
extern "C" void kernel_launch(void* const* d_in, const int* in_sizes, int n_in,
                              void* d_out, int out_size) {
    const float* feats      = (const float*)d_in[0];
    const long long* labels = (const long long*)d_in[1];
    float* out = (float*)d_out;

    cudaFuncSetAttribute(pairwise_kernel, cudaFuncAttributeMaxDynamicSharedMemorySize, SMEM_REQ);

    norm_kernel<<<N / 8, 256>>>(feats);
    pairwise_kernel<<<NBLK, 256, SMEM_REQ>>>(labels);
    rowreduce_kernel<<<N / 8, 256>>>();
    final_kernel<<<1, 256>>>(out);
}

// round 6
// speedup vs baseline: 6.1765x; 1.7010x over previous
#include <cuda_runtime.h>
#include <cuda_fp16.h>
#include <cstdint>

#define N 8192
#define D 128
#define TSZ 128
#define NTILE 64
#define NBLK (NTILE * (NTILE + 1) / 2)   // 2080 triangular blocks
#define NSPLIT 512                       // 64 tiles * 8 (wn*2 + role/wm)
#define TEMP_INV 10.0f

// ---------------- scratch (no cudaMalloc allowed) ----------------
__device__ unsigned short g_hi[N * D];       // fp16 normalized embeds, 2 MB
__device__ float g_Zp[(size_t)N * NSPLIT];   // 16 MB, zero-init; unwritten slots stay 0
__device__ float g_Sp[(size_t)N * NSPLIT];   // 16 MB
__device__ int   g_Pp[(size_t)N * NSPLIT];   // 16 MB
__device__ float g_blkL[N / 8];
__device__ float g_blkC[N / 8];

// ---------------- smem geometry ----------------
#define STRIDE_B 272                 // bytes per 128-half row (16B pad, conflict-free ldmatrix)
#define TILE_B   (128 * STRIDE_B)    // 34816
#define OF_A     0
#define OF_B     (TILE_B)
#define OF_LABA  (2 * TILE_B)        // 69632
#define OF_LABB  (OF_LABA + 512)
#define SMEM_REQ (OF_LABB + 512)     // 70656 -> 2 blocks/SM

__device__ __forceinline__ uint32_t smem_to_u32(const void* p) {
    uint32_t a;
    asm("{ .reg .u64 t; cvta.to.shared.u64 t, %1; cvt.u32.u64 %0, t; }" : "=r"(a) : "l"(p));
    return a;
}
__device__ __forceinline__ void ldsm4(uint32_t* r, uint32_t addr) {
    asm volatile("ldmatrix.sync.aligned.m8n8.x4.shared.b16 {%0,%1,%2,%3}, [%4];"
        : "=r"(r[0]), "=r"(r[1]), "=r"(r[2]), "=r"(r[3]) : "r"(addr));
}
__device__ __forceinline__ void mma16816(float* c, const uint32_t* a, const uint32_t* b) {
    asm volatile("mma.sync.aligned.m16n8k16.row.col.f32.f16.f16.f32 "
        "{%0,%1,%2,%3}, {%4,%5,%6,%7}, {%8,%9}, {%0,%1,%2,%3};"
        : "+f"(c[0]), "+f"(c[1]), "+f"(c[2]), "+f"(c[3])
        : "r"(a[0]), "r"(a[1]), "r"(a[2]), "r"(a[3]), "r"(b[0]), "r"(b[1]));
}

// ---------------------------------------------------------------------------
// Kernel 1: L2-normalize -> fp16. One warp per row.
// ---------------------------------------------------------------------------
__global__ void norm_kernel(const float* __restrict__ x) {
    int row  = blockIdx.x * 8 + (threadIdx.x >> 5);
    int lane = threadIdx.x & 31;
    const float4 v = *(const float4*)(x + row * D + lane * 4);
    float ss = v.x * v.x + v.y * v.y + v.z * v.z + v.w * v.w;
    #pragma unroll
    for (int o = 16; o >= 1; o >>= 1) ss += __shfl_xor_sync(0xffffffffu, ss, o);
    float r = rsqrtf(ss);
    unsigned short hs[4];
    float xs[4] = {v.x * r, v.y * r, v.z * r, v.w * r};
    #pragma unroll
    for (int i = 0; i < 4; ++i) hs[i] = __half_as_ushort(__float2half_rn(xs[i]));
    *(ushort4*)(g_hi + row * D + lane * 4) = make_ushort4(hs[0], hs[1], hs[2], hs[3]);
}

// ---------------------------------------------------------------------------
// Kernel 2: triangular 128x128 tiles (by <= bx), single-pass fp16 HMMA.
// Epilogue extracts row sums (rows i0..) and, off-diagonal, column sums
// (= mirror tile's row sums, rows j0..).
// Grid: NBLK 1D; 256 threads = 8 warps (2m x 4n); occupancy 2.
// ---------------------------------------------------------------------------
__global__ void __launch_bounds__(256, 2)
pairwise_kernel(const long long* __restrict__ labels) {
    // triangular decode: t -> (bx, by), 0 <= by <= bx < 64 (hardened)
    const int t = blockIdx.x;
    int bx = (int)((sqrtf(8.0f * (float)t + 1.0f) - 1.0f) * 0.5f);
    while ((bx + 1) * (bx + 2) / 2 <= t) ++bx;
    while (bx * (bx + 1) / 2 > t) --bx;
    const int by = t - bx * (bx + 1) / 2;
    const bool diag = (by == bx);

    extern __shared__ char smem[];
    const uint32_t smb = smem_to_u32(smem);

    const int tid  = threadIdx.x;
    const int wid  = tid >> 5;
    const int lane = tid & 31;
    const int wm   = wid >> 2;       // 0..1  -> 64-row slab
    const int wn   = wid & 3;        // 0..3  -> 32-col slab
    const int i0 = by * TSZ, j0 = bx * TSZ;

    // ---- fill smem tiles (A always; B only off-diagonal) ----
    {
        const char* ghi = (const char*)g_hi;
        #pragma unroll
        for (int it = 0; it < 8; ++it) {
            int idx   = it * 256 + tid;       // 0..2047
            int row   = idx >> 4;
            int chunk = idx & 15;
            uint4 v = *(const uint4*)(ghi + (size_t)(i0 + row) * 256 + chunk * 16);
            *(uint4*)(smem + OF_A + row * STRIDE_B + chunk * 16) = v;
        }
        if (!diag) {
            #pragma unroll
            for (int it = 0; it < 8; ++it) {
                int idx   = it * 256 + tid;
                int row   = idx >> 4;
                int chunk = idx & 15;
                uint4 v = *(const uint4*)(ghi + (size_t)(j0 + row) * 256 + chunk * 16);
                *(uint4*)(smem + OF_B + row * STRIDE_B + chunk * 16) = v;
            }
        }
        if (tid < 128) {
            ((int*)(smem + OF_LABA))[tid] = (int)labels[i0 + tid];
            ((int*)(smem + OF_LABB))[tid] = (int)labels[j0 + tid];
        }
    }
    __syncthreads();

    const uint32_t bTile = diag ? (uint32_t)OF_A : (uint32_t)OF_B;
    const uint32_t aBase = smb + (uint32_t)((wm * 64 + (lane & 15)) * STRIDE_B + (lane >> 4) * 16);
    const uint32_t bBase = smb + bTile
                         + (uint32_t)((wn * 32 + (lane & 7) + ((lane >> 4) << 3)) * STRIDE_B
                                      + ((lane >> 3) & 1) * 16);

    float acc[4][4][4];
    #pragma unroll
    for (int mi = 0; mi < 4; ++mi)
        #pragma unroll
        for (int ni = 0; ni < 4; ++ni)
            #pragma unroll
            for (int r = 0; r < 4; ++r) acc[mi][ni][r] = 0.f;

    #pragma unroll
    for (int ks = 0; ks < 8; ++ks) {
        const uint32_t ko = (uint32_t)(ks * 32);
        uint32_t a[4][4], b[4][2];
        #pragma unroll
        for (int mi = 0; mi < 4; ++mi)
            ldsm4(a[mi], aBase + mi * (16 * STRIDE_B) + ko);
        uint32_t t0[4], t1[4];
        ldsm4(t0, bBase + ko);
        ldsm4(t1, bBase + 16 * STRIDE_B + ko);
        b[0][0] = t0[0]; b[0][1] = t0[1]; b[1][0] = t0[2]; b[1][1] = t0[3];
        b[2][0] = t1[0]; b[2][1] = t1[1]; b[3][0] = t1[2]; b[3][1] = t1[3];

        #pragma unroll
        for (int mi = 0; mi < 4; ++mi)
            #pragma unroll
            for (int ni = 0; ni < 4; ++ni)
                mma16816(acc[mi][ni], a[mi], b[ni]);
    }

    // ---- fused epilogue ----
    const int tq = lane >> 2;       // 0..7
    const int tr = lane & 3;        // 0..3
    const int* labAs = (const int*)(smem + OF_LABA);
    const int* labBs = (const int*)(smem + OF_LABB);

    int labi[4][2];
    #pragma unroll
    for (int mi = 0; mi < 4; ++mi)
        #pragma unroll
        for (int h = 0; h < 2; ++h)
            labi[mi][h] = labAs[wm * 64 + mi * 16 + h * 8 + tq];

    float rz[4][2], rs[4][2], cz[4][2], cs[4][2];
    int   rp[4][2], cp[4][2];
    #pragma unroll
    for (int a = 0; a < 4; ++a)
        #pragma unroll
        for (int b = 0; b < 2; ++b) {
            rz[a][b] = rs[a][b] = cz[a][b] = cs[a][b] = 0.f;
            rp[a][b] = cp[a][b] = 0;
        }

    #pragma unroll
    for (int ni = 0; ni < 4; ++ni) {
        const int jc  = j0 + wn * 32 + ni * 8 + tr * 2;
        const int lj0 = labBs[wn * 32 + ni * 8 + tr * 2];
        const int lj1 = labBs[wn * 32 + ni * 8 + tr * 2 + 1];
        #pragma unroll
        for (int mi = 0; mi < 4; ++mi)
            #pragma unroll
            for (int h = 0; h < 2; ++h) {
                const int ig = i0 + wm * 64 + mi * 16 + h * 8 + tq;
                float l0 = acc[mi][ni][h * 2 + 0] * TEMP_INV;
                float l1 = acc[mi][ni][h * 2 + 1] * TEMP_INV;
                float e0 = __expf(l0), e1 = __expf(l1);
                bool m0 = (labi[mi][h] == lj0);
                bool m1 = (labi[mi][h] == lj1);
                if (!(diag && jc == ig))     { rz[mi][h] += e0; if (m0) { rs[mi][h] += l0; rp[mi][h] += 1; } }
                if (!(diag && jc + 1 == ig)) { rz[mi][h] += e1; if (m1) { rs[mi][h] += l1; rp[mi][h] += 1; } }
                cz[ni][0] += e0; if (m0) { cs[ni][0] += l0; cp[ni][0] += 1; }
                cz[ni][1] += e1; if (m1) { cs[ni][1] += l1; cp[ni][1] += 1; }
            }
    }

    // row partials: reduce over tr lanes (xor 1,2), split = bx*8 + wn*2
    {
        const int sp = bx * 8 + wn * 2;
        #pragma unroll
        for (int mi = 0; mi < 4; ++mi)
            #pragma unroll
            for (int h = 0; h < 2; ++h) {
                float zz = rz[mi][h], ss = rs[mi][h];
                int pp = rp[mi][h];
                #pragma unroll
                for (int o = 1; o <= 2; o <<= 1) {
                    zz += __shfl_xor_sync(0xffffffffu, zz, o);
                    ss += __shfl_xor_sync(0xffffffffu, ss, o);
                    pp += __shfl_xor_sync(0xffffffffu, pp, o);
                }
                if (tr == 0) {
                    int row = i0 + wm * 64 + mi * 16 + h * 8 + tq;
                    g_Zp[(size_t)row * NSPLIT + sp] = zz;
                    g_Sp[(size_t)row * NSPLIT + sp] = ss;
                    g_Pp[(size_t)row * NSPLIT + sp] = pp;
                }
            }
    }

    // column partials (mirror rows): reduce over tq lanes (xor 4,8,16),
    // split = by*8 + wn*2 + wm  (disjoint from row splits since by < bx)
    if (!diag) {
        const int sp = by * 8 + wn * 2 + wm;
        #pragma unroll
        for (int ni = 0; ni < 4; ++ni)
            #pragma unroll
            for (int c = 0; c < 2; ++c) {
                float zz = cz[ni][c], ss = cs[ni][c];
                int pp = cp[ni][c];
                #pragma unroll
                for (int o = 4; o <= 16; o <<= 1) {
                    zz += __shfl_xor_sync(0xffffffffu, zz, o);
                    ss += __shfl_xor_sync(0xffffffffu, ss, o);
                    pp += __shfl_xor_sync(0xffffffffu, pp, o);
                }
                if (tq == 0) {
                    int row = j0 + wn * 32 + ni * 8 + tr * 2 + c;
                    g_Zp[(size_t)row * NSPLIT + sp] = zz;
                    g_Sp[(size_t)row * NSPLIT + sp] = ss;
                    g_Pp[(size_t)row * NSPLIT + sp] = pp;
                }
            }
    }
}

// ---------------------------------------------------------------------------
// Kernel 3: per-row combine (warp per row) + per-block loss partial
// ---------------------------------------------------------------------------
__global__ void rowreduce_kernel() {
    __shared__ float bl[8], bc[8];
    const int warp = threadIdx.x >> 5;
    const int row  = blockIdx.x * 8 + warp;
    const int lane = threadIdx.x & 31;
    float z = 0.f, s = 0.f;
    int p = 0;
    #pragma unroll
    for (int k = 0; k < NSPLIT / 32; ++k) {
        int sp = lane + 32 * k;
        z += g_Zp[(size_t)row * NSPLIT + sp];
        s += g_Sp[(size_t)row * NSPLIT + sp];
        p += g_Pp[(size_t)row * NSPLIT + sp];
    }
    #pragma unroll
    for (int o = 16; o >= 1; o >>= 1) {
        z += __shfl_xor_sync(0xffffffffu, z, o);
        s += __shfl_xor_sync(0xffffffffu, s, o);
        p += __shfl_xor_sync(0xffffffffu, p, o);
    }
    if (lane == 0) {
        if (p > 0) { bl[warp] = s / (float)p - logf(z); bc[warp] = 1.f; }
        else       { bl[warp] = 0.f;                    bc[warp] = 0.f; }
    }
    __syncthreads();
    if (threadIdx.x == 0) {
        float L = 0.f, C = 0.f;
        #pragma unroll
        for (int w = 0; w < 8; ++w) { L += bl[w]; C += bc[w]; }
        g_blkL[blockIdx.x] = L;
        g_blkC[blockIdx.x] = C;
    }
}

// ---------------------------------------------------------------------------
// Kernel 4: final scalar over N/8 = 1024 block partials
// ---------------------------------------------------------------------------
__global__ void final_kernel(float* __restrict__ out) {
    __shared__ float s_l[256], s_c[256];
    const int tid = threadIdx.x;
    float lsum = 0.f, vcnt = 0.f;
    #pragma unroll
    for (int k = 0; k < 4; ++k) {
        lsum += g_blkL[tid + 256 * k];
        vcnt += g_blkC[tid + 256 * k];
    }
    s_l[tid] = lsum; s_c[tid] = vcnt;
    __syncthreads();
    for (int o = 128; o >= 1; o >>= 1) {
        if (tid < o) { s_l[tid] += s_l[tid + o]; s_c[tid] += s_c[tid + o]; }
        __syncthreads();
    }
    if (tid == 0) out[0] = -s_l[0] / s_c[0];
}

// ---------------------------------------------------------------------------
extern "C" void kernel_launch(void* const* d_in, const int* in_sizes, int n_in,
                              void* d_out, int out_size) {
    const float* feats      = (const float*)d_in[0];
    const long long* labels = (const long long*)d_in[1];
    float* out = (float*)d_out;

    cudaFuncSetAttribute(pairwise_kernel, cudaFuncAttributeMaxDynamicSharedMemorySize, SMEM_REQ);

    norm_kernel<<<N / 8, 256>>>(feats);
    pairwise_kernel<<<NBLK, 256, SMEM_REQ>>>(labels);
    rowreduce_kernel<<<N / 8, 256>>>();
    final_kernel<<<1, 256>>>(out);
}